// round 14
// baseline (speedup 1.0000x reference)
#include <cuda_runtime.h>
#include <cuda_bf16.h>
#include <math.h>
#include <stdint.h>

#define NN 10000
#define EE 160000
#define BB 16
#define HH 64
#define AA 8
#define LL 2
#define MSGIN 131
#define UPDIN 129

// ---------------- scratch (device globals) ----------------------------------
__device__ float g_h[NN * HH];
__device__ float g_agg[NN * HH];
__device__ float g_pool[BB * HH];
__device__ float g_cnt[BB];
__device__ float g_T1[NN * 512];
__device__ float g_T2[NN * 512];
// split-bf16 weight planes
__device__ __align__(16) __nv_bfloat16 g_W2h[2][8][64][72];
__device__ __align__(16) __nv_bfloat16 g_W2l[2][8][64][72];
__device__ __align__(16) __nv_bfloat16 g_U1h[2][8][64][152];
__device__ __align__(16) __nv_bfloat16 g_U1l[2][8][64][152];
__device__ __align__(16) __nv_bfloat16 g_U2h[2][8][64][72];
__device__ __align__(16) __nv_bfloat16 g_U2l[2][8][64][72];
__device__ __align__(16) __nv_bfloat16 g_P1h[8][64][72];
__device__ __align__(16) __nv_bfloat16 g_P1l[8][64][72];
__device__ __align__(16) __nv_bfloat16 g_P2h[8][64][72];
__device__ __align__(16) __nv_bfloat16 g_P2l[8][64][72];
// W1 permuted planes for nodeT GEMM: [l][chunk 0..15][col 64][i 88]
__device__ __align__(16) __nv_bfloat16 g_TWh[2][16][64][88];
__device__ __align__(16) __nv_bfloat16 g_TWl[2][16][64][88];

__device__ __forceinline__ float silu_f(float x) { return x / (1.0f + expf(-x)); }

// ---------------- PTX helpers (generic sm_80+) -------------------------------
__device__ __forceinline__ uint32_t smem_u32_of(const void* p) {
    uint32_t a;
    asm("{ .reg .u64 t; cvta.to.shared.u64 t, %1; cvt.u32.u64 %0, t; }" : "=r"(a) : "l"(p));
    return a;
}
__device__ __forceinline__ void mma_bf16(float (&c)[4], const uint32_t (&a)[4],
                                         uint32_t b0, uint32_t b1) {
    asm volatile(
        "mma.sync.aligned.m16n8k16.row.col.f32.bf16.bf16.f32 "
        "{%0,%1,%2,%3}, {%4,%5,%6,%7}, {%8,%9}, {%0,%1,%2,%3};"
        : "+f"(c[0]), "+f"(c[1]), "+f"(c[2]), "+f"(c[3])
        : "r"(a[0]), "r"(a[1]), "r"(a[2]), "r"(a[3]), "r"(b0), "r"(b1));
}
__device__ __forceinline__ void ldmx4(uint32_t& r0, uint32_t& r1, uint32_t& r2, uint32_t& r3,
                                      uint32_t addr) {
    asm volatile("ldmatrix.sync.aligned.m8n8.x4.shared.b16 {%0,%1,%2,%3}, [%4];"
                 : "=r"(r0), "=r"(r1), "=r"(r2), "=r"(r3) : "r"(addr));
}
__device__ __forceinline__ void cp_async16(uint32_t smem_addr, const void* gptr) {
    asm volatile("cp.async.cg.shared.global [%0], [%1], 16;"
                 :: "r"(smem_addr), "l"(gptr) : "memory");
}
__device__ __forceinline__ void cp_commit() {
    asm volatile("cp.async.commit_group;" ::: "memory");
}
__device__ __forceinline__ void cp_wait0() {
    asm volatile("cp.async.wait_group 0;" ::: "memory");
}
__device__ __forceinline__ uint32_t pack2_bf16(__nv_bfloat16 lo16, __nv_bfloat16 hi16) {
    uint16_t a, b;
    memcpy(&a, &lo16, 2);
    memcpy(&b, &hi16, 2);
    return (uint32_t)a | ((uint32_t)b << 16);
}
__device__ __forceinline__ void split_pack(float v0, float v1, uint32_t& hw, uint32_t& lw) {
    __nv_bfloat16 h0 = __float2bfloat16(v0);
    __nv_bfloat16 h1 = __float2bfloat16(v1);
    __nv_bfloat16 l0 = __float2bfloat16(v0 - __bfloat162float(h0));
    __nv_bfloat16 l1 = __float2bfloat16(v1 - __bfloat162float(h1));
    hw = pack2_bf16(h0, h1);
    lw = pack2_bf16(l0, l1);
}

// ============================================================================
// scalar node-side TP core (embed only)
// ============================================================================
__device__ __forceinline__ void tp4(float (&acc)[4][8], const float* s_in, int stride,
                                    const float* s_W, const float (&av)[4][8],
                                    int nrow0, int kbase, int ilen)
{
    for (int i = 0; i < ilen; ++i) {
        float m0 = s_in[(nrow0 + 0) * stride + i];
        float m1 = s_in[(nrow0 + 1) * stride + i];
        float m2 = s_in[(nrow0 + 2) * stride + i];
        float m3 = s_in[(nrow0 + 3) * stride + i];
        const float* wrow = s_W + i * 512 + kbase;
#pragma unroll
        for (int j = 0; j < 8; ++j) {
            float4 wa = *(const float4*)(wrow + j * 64);
            float4 wb = *(const float4*)(wrow + j * 64 + 4);
            float w[8] = {wa.x, wa.y, wa.z, wa.w, wb.x, wb.y, wb.z, wb.w};
            float c0 = m0 * av[0][j];
            float c1 = m1 * av[1][j];
            float c2 = m2 * av[2][j];
            float c3 = m3 * av[3][j];
#pragma unroll
            for (int t = 0; t < 8; ++t) {
                acc[0][t] = fmaf(c0, w[t], acc[0][t]);
                acc[1][t] = fmaf(c1, w[t], acc[1][t]);
                acc[2][t] = fmaf(c2, w[t], acc[2][t]);
                acc[3][t] = fmaf(c3, w[t], acc[3][t]);
            }
        }
    }
}

__device__ __forceinline__ void stage_w128(float* s_W, const float* Wg, int ibase, int ilen)
{
    const float4* src = (const float4*)(Wg + (size_t)ibase * 512);
    float4* dst = (float4*)s_W;
    int n4 = ilen * 128;
    for (int idx = threadIdx.x; idx < n4; idx += 128) dst[idx] = src[idx];
}

// ================= merged prep kernel =======================================
__global__ void __launch_bounds__(256)
prep_all_kernel(const float* __restrict__ Wm1, const float* __restrict__ Wm2,
                const float* __restrict__ Wu1, const float* __restrict__ Wu2,
                const float* __restrict__ Wp1, const float* __restrict__ Wp2)
{
    int idx = blockIdx.x * 256 + threadIdx.x;
    float v;
    __nv_bfloat16 *ph, *pl;

    if (idx < 65536) {
        int l = idx >> 15, rem = idx & 32767;
        int c = rem >> 12, r2 = rem & 4095;
        int n = r2 >> 6, i = r2 & 63;
        v = Wm2[(size_t)l * 64 * 512 + (size_t)i * 512 + c * 64 + n];
        ph = &g_W2h[l][c][n][i]; pl = &g_W2l[l][c][n][i];
    } else if (idx < 65536 + 155648) {
        int q = idx - 65536;
        int l = q / 77824, rem = q - l * 77824;
        int c = rem / 9728, r2 = rem - c * 9728;
        int n = r2 / 152, i = r2 - n * 152;
        v = (i < UPDIN) ? Wu1[(size_t)l * UPDIN * 512 + (size_t)i * 512 + c * 64 + n] : 0.0f;
        ph = &g_U1h[l][c][n][i]; pl = &g_U1l[l][c][n][i];
    } else if (idx < 65536 + 155648 + 73728) {
        int q = idx - 65536 - 155648;
        int l = q / 36864, rem = q - l * 36864;
        int c = rem / 4608, r2 = rem - c * 4608;
        int n = r2 / 72, i = r2 - n * 72;
        v = (i < 64) ? Wu2[(size_t)l * 64 * 512 + (size_t)i * 512 + c * 64 + n] : 0.0f;
        ph = &g_U2h[l][c][n][i]; pl = &g_U2l[l][c][n][i];
    } else if (idx < 65536 + 155648 + 73728 + 73728) {
        int q = idx - 65536 - 155648 - 73728;
        int sel = q / 36864, rem = q - sel * 36864;
        int c = rem / 4608, r2 = rem - c * 4608;
        int n = r2 / 72, i = r2 - n * 72;
        const float* W = sel ? Wp2 : Wp1;
        v = (i < 64) ? W[(size_t)i * 512 + c * 64 + n] : 0.0f;
        if (sel) { ph = &g_P2h[c][n][i]; pl = &g_P2l[c][n][i]; }
        else     { ph = &g_P1h[c][n][i]; pl = &g_P1l[c][n][i]; }
    } else if (idx < 65536 + 155648 + 73728 + 73728 + 180224) {
        int q = idx - 65536 - 155648 - 73728 - 73728;
        int l = q / 90112, rem = q - l * 90112;
        int c = rem / 5632, r2 = rem - c * 5632;
        int n = r2 / 88, i = r2 - n * 88;
        int g = (c & 7) * 64 + n;
        int j = g & 7, kk = g >> 3;
        int wrow = (c < 8) ? i : (65 + i);
        v = (i < 65) ? Wm1[(size_t)l * MSGIN * 512 + (size_t)wrow * 512 + j * 64 + kk] : 0.0f;
        ph = &g_TWh[l][c][n][i]; pl = &g_TWl[l][c][n][i];
    } else return;

    __nv_bfloat16 h = __float2bfloat16(v);
    *ph = h;
    *pl = __float2bfloat16(v - __bfloat162float(h));
}

// ================= nodeT MMA kernel (round-13, unchanged) ===================
#define TM_AH 0
#define TM_AL 11264
#define TM_B  22528
#define TM_BYTES (22528 + 45056)
#define TRS 176

__global__ void __launch_bounds__(256, 2)
nodeT_mma_kernel(int l, const float* __restrict__ anf)
{
    extern __shared__ float sm[];
    char* smc = (char*)sm;
    char* pAh = smc + TM_AH;
    char* pAl = smc + TM_AL;
    uint32_t bB = smem_u32_of(smc + TM_B);

    int tid = threadIdx.x;
    int w = tid >> 5, lane = tid & 31;
    int n0 = blockIdx.x * 64;

    {
        const char* srch = (const char*)(&g_TWh[l][0][0][0]);
        const char* srcl = (const char*)(&g_TWl[l][0][0][0]);
        for (int idx = tid; idx < 1408; idx += 256) {
            if (idx < 704) cp_async16(bB + idx * 16, srch + idx * 16);
            else cp_async16(bB + 11264 + (idx - 704) * 16, srcl + (idx - 704) * 16);
        }
        cp_commit();
    }

    for (int idx = tid; idx < 64 * 16; idx += 256) {
        int row = idx >> 4, q = idx & 15;
        int n = n0 + row;
        if (n < NN)
            *(float4*)(g_agg + (size_t)n * 64 + q * 4) = make_float4(0.f, 0.f, 0.f, 0.f);
    }

    for (int idx = tid; idx < 64 * 40; idx += 256) {
        int row = idx / 40, iw = idx - row * 40;
        int n = min(n0 + row, NN - 1);
        int i0 = iw * 2;
        float v0 = (i0 < 64) ? g_h[n * 64 + i0] : ((i0 == 64) ? anf[n] : 0.0f);
        float v1 = (i0 + 1 < 64) ? g_h[n * 64 + i0 + 1] : ((i0 + 1 == 64) ? anf[n] : 0.0f);
        uint32_t hw, lw;
        split_pack(v0, v1, hw, lw);
        uint32_t off = (uint32_t)(row * TRS + i0 * 2);
        *(uint32_t*)(pAh + off) = hw;
        *(uint32_t*)(pAl + off) = lw;
    }
    __syncthreads();

    int wr = w & 3, nh = w >> 2;
    int g = lane >> 2, t = lane & 3;
    int r0 = wr * 16 + g, r1 = r0 + 8;

    uint32_t shAh = smem_u32_of(pAh) +
        (uint32_t)((wr * 16 + (lane & 15)) * TRS + ((lane >> 4) & 1) * 16);
    uint32_t shAl = shAh + 11264;
    uint32_t ah[5][4], al[5][4];
#pragma unroll
    for (int kt = 0; kt < 5; ++kt) {
        ldmx4(ah[kt][0], ah[kt][1], ah[kt][2], ah[kt][3], shAh + kt * 32);
        ldmx4(al[kt][0], al[kt][1], al[kt][2], al[kt][3], shAl + kt * 32);
    }

    uint32_t bo0 = (uint32_t)(((lane & 7) + ((lane >> 4) & 1) * 8) * TRS +
                              ((lane >> 3) & 1) * 16 + nh * 32 * TRS);

    for (int c = 0; c < 16; ++c) {
        cp_wait0();
        __syncthreads();
        if (c < 15) {
            const char* srch = (const char*)(&g_TWh[l][c + 1][0][0]);
            const char* srcl = (const char*)(&g_TWl[l][c + 1][0][0]);
            uint32_t nb = bB + ((c + 1) & 1) * 22528;
            for (int idx = tid; idx < 1408; idx += 256) {
                if (idx < 704) cp_async16(nb + idx * 16, srch + idx * 16);
                else cp_async16(nb + 11264 + (idx - 704) * 16, srcl + (idx - 704) * 16);
            }
            cp_commit();
        }

        uint32_t bb = bB + (c & 1) * 22528;

        float acc[4][4];
#pragma unroll
        for (int nt = 0; nt < 4; ++nt)
#pragma unroll
            for (int q = 0; q < 4; ++q) acc[nt][q] = 0.0f;

#pragma unroll
        for (int kt = 0; kt < 5; ++kt) {
            uint32_t ko = (uint32_t)(kt * 32);
#pragma unroll
            for (int p = 0; p < 2; ++p) {
                uint32_t bo = bo0 + (uint32_t)(p * 16 * TRS) + ko;
                uint32_t bh0, bh1, bh2, bh3, bl0, bl1, bl2, bl3;
                ldmx4(bh0, bh1, bh2, bh3, bb + bo);
                ldmx4(bl0, bl1, bl2, bl3, bb + 11264 + bo);
                mma_bf16(acc[2 * p],     ah[kt], bh0, bh1);
                mma_bf16(acc[2 * p],     ah[kt], bl0, bl1);
                mma_bf16(acc[2 * p],     al[kt], bh0, bh1);
                mma_bf16(acc[2 * p + 1], ah[kt], bh2, bh3);
                mma_bf16(acc[2 * p + 1], ah[kt], bl2, bl3);
                mma_bf16(acc[2 * p + 1], al[kt], bh2, bh3);
            }
        }

        float* T = (c < 8) ? g_T1 : g_T2;
        int cb = (c & 7) * 64;
        int na = n0 + r0, nb2 = n0 + r1;
#pragma unroll
        for (int nt = 0; nt < 4; ++nt) {
            int col = cb + nh * 32 + nt * 8 + 2 * t;
            if (na < NN) {
                T[(size_t)na * 512 + col]     = acc[nt][0];
                T[(size_t)na * 512 + col + 1] = acc[nt][1];
            }
            if (nb2 < NN) {
                T[(size_t)nb2 * 512 + col]     = acc[nt][2];
                T[(size_t)nb2 * 512 + col + 1] = acc[nt][3];
            }
        }
    }
}

// ================= msg kernel v7 (unchanged) ================================
#define MH_A_HI 0
#define MH_A_LO 18432
#define MH_B    36864
#define MH_A8   73728
#define MH_WAMF 77824
#define MH_B1   79872
#define MH_B2   80128
#define MH_IDX  80384
#define MH_BYTES 81408

#define ARS 144
#define BRS 144

__global__ void __launch_bounds__(256, 2)
msg_kernel_v7(int l, const int* __restrict__ edge_index, const float* __restrict__ edge_attr,
              const float* __restrict__ amf,
              const float* __restrict__ Wm1, const float* __restrict__ bm1,
              const float* __restrict__ bm2)
{
    extern __shared__ float sm[];
    char*  smc    = (char*)sm;
    char*  pAh    = smc + MH_A_HI;
    char*  pAl    = smc + MH_A_LO;
    float* s_a    = (float*)(smc + MH_A8);
    float* s_wamf = (float*)(smc + MH_WAMF);
    float* s_b1   = (float*)(smc + MH_B1);
    float* s_b2   = (float*)(smc + MH_B2);
    int*   s_src  = (int*)(smc + MH_IDX);
    int*   s_dst  = s_src + 128;

    int tid = threadIdx.x;
    int w = tid >> 5, lane = tid & 31;
    int e_abs0 = blockIdx.x * 128;
    const float* W1l = Wm1 + (size_t)l * MSGIN * 512;

    uint32_t bufBase0 = smem_u32_of(smc + MH_B);
    uint32_t bufBase1 = bufBase0 + 18432;

    {
        const char* srch = (const char*)(&g_W2h[l][0][0][0]);
        const char* srcl = (const char*)(&g_W2l[l][0][0][0]);
        for (int idx = tid; idx < 1152; idx += 256) {
            if (idx < 576) cp_async16(bufBase0 + idx * 16, srch + idx * 16);
            else cp_async16(bufBase0 + 9216 + (idx - 576) * 16, srcl + (idx - 576) * 16);
        }
        cp_commit();
    }

    if (tid < 128) {
        s_src[tid] = edge_index[e_abs0 + tid];
        s_dst[tid] = edge_index[EE + e_abs0 + tid];
    }
    for (int idx = tid; idx < 1024; idx += 256)
        s_a[idx] = edge_attr[(size_t)e_abs0 * 8 + idx];
    for (int idx = tid; idx < 512; idx += 256) {
        int k = idx >> 3, j = idx & 7;
        s_wamf[idx] = W1l[(size_t)130 * 512 + j * 64 + k];
    }
    if (tid < 64) {
        s_b1[tid] = bm1[l * 64 + tid];
        s_b2[tid] = bm2[l * 64 + tid];
    }
    __syncthreads();

    {
        int jb = (lane & 1) * 4;
        int klo = lane >> 1;
#pragma unroll 2
        for (int t = 0; t < 16; ++t) {
            int e = w * 16 + t;
            int d = s_dst[e], sn = s_src[e];
            float amfv = amf[e_abs0 + e];
            float a0 = s_a[e * 8 + jb + 0];
            float a1 = s_a[e * 8 + jb + 1];
            float a2 = s_a[e * 8 + jb + 2];
            float a3 = s_a[e * 8 + jb + 3];
            const float4* T1p = (const float4*)(g_T1 + (size_t)d * 512);
            const float4* T2p = (const float4*)(g_T2 + (size_t)sn * 512);
            const float4* Wap = (const float4*)s_wamf;

            float rk[4];
#pragma unroll
            for (int r = 0; r < 4; ++r) {
                int fi = r * 32 + lane;
                float4 t1 = T1p[fi];
                float4 t2 = T2p[fi];
                float4 wa = Wap[fi];
                float p;
                p  = (t1.x + t2.x + amfv * wa.x) * a0;
                p += (t1.y + t2.y + amfv * wa.y) * a1;
                p += (t1.z + t2.z + amfv * wa.z) * a2;
                p += (t1.w + t2.w + amfv * wa.w) * a3;
                p += __shfl_xor_sync(0xffffffffu, p, 1);
                rk[r] = p;
            }
            if (!(lane & 1)) {
#pragma unroll
                for (int r = 0; r < 4; ++r) {
                    int kk = r * 16 + klo;
                    float v = silu_f(rk[r] + s_b1[kk]);
                    __nv_bfloat16 h = __float2bfloat16(v);
                    __nv_bfloat16 lo = __float2bfloat16(v - __bfloat162float(h));
                    uint32_t off = (uint32_t)(e * ARS + kk * 2);
                    *(__nv_bfloat16*)(pAh + off) = h;
                    *(__nv_bfloat16*)(pAl + off) = lo;
                }
            }
        }
    }
    __syncthreads();

    int g = lane >> 2, t = lane & 3;

    uint32_t aoff = (uint32_t)((w * 16 + (lane & 15)) * ARS + ((lane >> 4) & 1) * 16);
    uint32_t boff = (uint32_t)(((lane & 7) + ((lane >> 4) & 1) * 8) * BRS + ((lane >> 3) & 1) * 16);
    uint32_t shAh = smem_u32_of(pAh) + aoff;
    uint32_t shAl = smem_u32_of(pAl) + aoff;

    uint32_t ah[4][4], al[4][4];
#pragma unroll
    for (int kt = 0; kt < 4; ++kt) {
        ldmx4(ah[kt][0], ah[kt][1], ah[kt][2], ah[kt][3], shAh + kt * 32);
        ldmx4(al[kt][0], al[kt][1], al[kt][2], al[kt][3], shAl + kt * 32);
    }

    int r0 = w * 16 + g, r1 = r0 + 8;

    float acc[8][4];
#pragma unroll
    for (int nt = 0; nt < 8; ++nt)
#pragma unroll
        for (int q = 0; q < 4; ++q) acc[nt][q] = 0.0f;

    for (int j = 0; j < 8; ++j) {
        cp_wait0();
        __syncthreads();
        if (j < 7) {
            const char* srch = (const char*)(&g_W2h[l][j + 1][0][0]);
            const char* srcl = (const char*)(&g_W2l[l][j + 1][0][0]);
            uint32_t nb = ((j + 1) & 1) ? bufBase1 : bufBase0;
            for (int idx = tid; idx < 1152; idx += 256) {
                if (idx < 576) cp_async16(nb + idx * 16, srch + idx * 16);
                else cp_async16(nb + 9216 + (idx - 576) * 16, srcl + (idx - 576) * 16);
            }
            cp_commit();
        }

        uint32_t bb = ((j & 1) ? bufBase1 : bufBase0) + boff;

        float P[8][4];
#pragma unroll
        for (int nt = 0; nt < 8; ++nt)
#pragma unroll
            for (int q = 0; q < 4; ++q) P[nt][q] = 0.0f;

#pragma unroll
        for (int kt = 0; kt < 4; ++kt) {
            uint32_t ko = (uint32_t)(kt * 32);
#pragma unroll
            for (int p = 0; p < 4; ++p) {
                uint32_t bo = (uint32_t)(p * 16 * BRS) + ko;
                uint32_t bh0, bh1, bh2, bh3, bl0, bl1, bl2, bl3;
                ldmx4(bh0, bh1, bh2, bh3, bb + bo);
                ldmx4(bl0, bl1, bl2, bl3, bb + 9216 + bo);
                mma_bf16(P[2 * p],     ah[kt], bh0, bh1);
                mma_bf16(P[2 * p],     ah[kt], bl0, bl1);
                mma_bf16(P[2 * p],     al[kt], bh0, bh1);
                mma_bf16(P[2 * p + 1], ah[kt], bh2, bh3);
                mma_bf16(P[2 * p + 1], ah[kt], bl2, bl3);
                mma_bf16(P[2 * p + 1], al[kt], bh2, bh3);
            }
        }

        float a0 = s_a[r0 * 8 + j];
        float a1 = s_a[r1 * 8 + j];
#pragma unroll
        for (int nt = 0; nt < 8; ++nt) {
            acc[nt][0] = fmaf(a0, P[nt][0], acc[nt][0]);
            acc[nt][1] = fmaf(a0, P[nt][1], acc[nt][1]);
            acc[nt][2] = fmaf(a1, P[nt][2], acc[nt][2]);
            acc[nt][3] = fmaf(a1, P[nt][3], acc[nt][3]);
        }
    }

    {
        int d0 = s_dst[r0], d1 = s_dst[r1];
        float* agg0 = g_agg + (size_t)d0 * 64;
        float* agg1 = g_agg + (size_t)d1 * 64;
#pragma unroll
        for (int nt = 0; nt < 8; ++nt) {
            int c0 = nt * 8 + 2 * t, c1 = c0 + 1;
            atomicAdd(agg0 + c0, silu_f(acc[nt][0] + s_b2[c0]));
            atomicAdd(agg0 + c1, silu_f(acc[nt][1] + s_b2[c1]));
            atomicAdd(agg1 + c0, silu_f(acc[nt][2] + s_b2[c0]));
            atomicAdd(agg1 + c1, silu_f(acc[nt][3] + s_b2[c1]));
        }
    }
}

// ================= embed kernel v4 (unchanged) ==============================
#define E4_OFF_W  0
#define E4_OFF_IN 8704
#define E4_OFF_A  (8704 + 1344)
#define E4_FLOATS (8704 + 1344 + 512)
#define E4_BYTES  (E4_FLOATS * 4)

__global__ void __launch_bounds__(128, 2)
embed_kernel_v4(const float* __restrict__ x, const float* __restrict__ anf,
                const float* __restrict__ node_attr,
                const float* __restrict__ W_emb, const float* __restrict__ b_emb)
{
    extern __shared__ float sm[];
    float* s_W  = sm + E4_OFF_W;
    float* s_in = sm + E4_OFF_IN;
    float* s_a  = sm + E4_OFF_A;

    int tid = threadIdx.x;
    int wid = tid >> 5, lane = tid & 31;
    int n0 = blockIdx.x * 64;

    stage_w128(s_W, W_emb, 0, 17);
    for (int row = wid; row < 64; row += 4) {
        int n = min(n0 + row, NN - 1);
        if (lane < 17)
            s_in[row * 21 + lane] = (lane < 16) ? x[n * 16 + lane] : anf[n];
        if (lane < 8)
            s_a[row * 8 + lane] = node_attr[n * 8 + lane];
    }
    __syncthreads();

    int ng = tid >> 3, kq = tid & 7;
    int nrow0 = ng * 4, kbase = kq * 8;

    float av[4][8];
#pragma unroll
    for (int s = 0; s < 4; ++s)
#pragma unroll
        for (int j = 0; j < 8; ++j) av[s][j] = s_a[(nrow0 + s) * 8 + j];

    float acc[4][8];
#pragma unroll
    for (int t = 0; t < 8; ++t) {
        float b = b_emb[kbase + t];
        acc[0][t] = b; acc[1][t] = b; acc[2][t] = b; acc[3][t] = b;
    }

    tp4(acc, s_in, 21, s_W, av, nrow0, kbase, 17);

#pragma unroll
    for (int s = 0; s < 4; ++s) {
        int n = n0 + nrow0 + s;
        if (n < NN) {
#pragma unroll
            for (int t = 0; t < 8; ++t) g_h[n * 64 + kbase + t] = acc[s][t];
        }
    }
}

// ================= upd kernel MMA v2: half-chunk pipelined B ================
#define UA_A1H 0
#define UA_A1L 19456
#define UA_B   38912
#define UA_A2H 77824
#define UA_A2L 87040
#define UA_NA  96256
#define UA_B1  98304
#define UA_B2  98560
#define UA_BYTES 98816

#define ARS1 304

__device__ __forceinline__ float upd_in_val(int n, int i, const float* anf) {
    if (i < 64) return g_h[n * 64 + i];
    if (i == 64) return anf[n];
    if (i < UPDIN) return g_agg[n * 64 + (i - 65)];
    return 0.0f;
}

__global__ void __launch_bounds__(256, 2)
upd_mma_kernel(int l, const float* __restrict__ node_attr, const float* __restrict__ anf,
               const float* __restrict__ bu1, const float* __restrict__ bu2)
{
    extern __shared__ float sm[];
    char* smc = (char*)sm;
    char* pA1h = smc + UA_A1H;
    char* pA1l = smc + UA_A1L;
    char* pA2h = smc + UA_A2H;
    char* pA2l = smc + UA_A2L;
    float* s_na = (float*)(smc + UA_NA);
    float* s_b1 = (float*)(smc + UA_B1);
    float* s_b2 = (float*)(smc + UA_B2);
    uint32_t bB = smem_u32_of(smc + UA_B);

    int tid = threadIdx.x;
    int w = tid >> 5, lane = tid & 31;
    int n0 = blockIdx.x * 64;

    // prefetch TP1 lo half of chunk 0 (overlaps A build)
    {
        const char* srcl = (const char*)(&g_U1l[l][0][0][0]);
        for (int idx = tid; idx < 1216; idx += 256)
            cp_async16(bB + 19456 + idx * 16, srcl + idx * 16);
        cp_commit();
    }

    for (int idx = tid; idx < 512; idx += 256) {
        int row = idx >> 3, j = idx & 7;
        int n = min(n0 + row, NN - 1);
        s_na[idx] = node_attr[n * 8 + j];
    }
    if (tid < 64) {
        s_b1[tid] = bu1[l * 64 + tid];
        s_b2[tid] = bu2[l * 64 + tid];
    }

    for (int idx = tid; idx < 64 * 76; idx += 256) {
        int row = idx / 76, iw = idx - row * 76;
        int n = min(n0 + row, NN - 1);
        int i0 = iw * 2;
        float v0 = upd_in_val(n, i0, anf);
        float v1 = upd_in_val(n, i0 + 1, anf);
        uint32_t hw, lw;
        split_pack(v0, v1, hw, lw);
        uint32_t off = (uint32_t)(row * ARS1 + i0 * 2);
        *(uint32_t*)(pA1h + off) = hw;
        *(uint32_t*)(pA1l + off) = lw;
    }
    __syncthreads();

    int wr = w & 3, nh = w >> 2;
    int g = lane >> 2, t = lane & 3;
    int r0 = wr * 16 + g, r1 = r0 + 8;

    float acc1[4][4];
#pragma unroll
    for (int nt = 0; nt < 4; ++nt)
#pragma unroll
        for (int q = 0; q < 4; ++q) acc1[nt][q] = 0.0f;

    // ---- TP1: K=144 (9 kt), B rows 304B, half-chunk pipelined
    {
        uint32_t shAh = smem_u32_of(pA1h) +
            (uint32_t)((wr * 16 + (lane & 15)) * ARS1 + ((lane >> 4) & 1) * 16);
        uint32_t shAl = shAh + 19456;
        uint32_t bo0 = (uint32_t)(((lane & 7) + ((lane >> 4) & 1) * 8) * ARS1 +
                                  ((lane >> 3) & 1) * 16 + nh * 32 * ARS1);
        uint32_t bBh = bB, bBl = bB + 19456;

        for (int j = 0; j < 8; ++j) {
            cp_wait0();            // bl_j ready
            __syncthreads();
            {   // issue hi_j (overlaps LO pass)
                const char* srch = (const char*)(&g_U1h[l][j][0][0]);
                for (int idx = tid; idx < 1216; idx += 256)
                    cp_async16(bBh + idx * 16, srch + idx * 16);
                cp_commit();
            }

            float P[4][4];
#pragma unroll
            for (int nt = 0; nt < 4; ++nt)
#pragma unroll
                for (int q = 0; q < 4; ++q) P[nt][q] = 0.0f;

            // LO pass: ah x bl
#pragma unroll
            for (int kt = 0; kt < 9; ++kt) {
                uint32_t ko = (uint32_t)(kt * 32);
                uint32_t ah[4];
                ldmx4(ah[0], ah[1], ah[2], ah[3], shAh + ko);
#pragma unroll
                for (int p = 0; p < 2; ++p) {
                    uint32_t bo = bo0 + (uint32_t)(p * 16 * ARS1) + ko;
                    uint32_t bl0, bl1, bl2, bl3;
                    ldmx4(bl0, bl1, bl2, bl3, bBl + bo);
                    mma_bf16(P[2 * p],     ah, bl0, bl1);
                    mma_bf16(P[2 * p + 1], ah, bl2, bl3);
                }
            }

            cp_wait0();            // bh_j ready; sync ensures LO pass done block-wide
            __syncthreads();
            if (j < 7) {           // issue lo_{j+1} (overlaps HI passes)
                const char* srcl = (const char*)(&g_U1l[l][j + 1][0][0]);
                for (int idx = tid; idx < 1216; idx += 256)
                    cp_async16(bBl + idx * 16, srcl + idx * 16);
                cp_commit();
            }

            // HI passes: ah x bh, al x bh
#pragma unroll
            for (int kt = 0; kt < 9; ++kt) {
                uint32_t ko = (uint32_t)(kt * 32);
                uint32_t ah[4], al[4];
                ldmx4(ah[0], ah[1], ah[2], ah[3], shAh + ko);
                ldmx4(al[0], al[1], al[2], al[3], shAl + ko);
#pragma unroll
                for (int p = 0; p < 2; ++p) {
                    uint32_t bo = bo0 + (uint32_t)(p * 16 * ARS1) + ko;
                    uint32_t bh0, bh1, bh2, bh3;
                    ldmx4(bh0, bh1, bh2, bh3, bBh + bo);
                    mma_bf16(P[2 * p],     ah, bh0, bh1);
                    mma_bf16(P[2 * p],     al, bh0, bh1);
                    mma_bf16(P[2 * p + 1], ah, bh2, bh3);
                    mma_bf16(P[2 * p + 1], al, bh2, bh3);
                }
            }

            float a0 = s_na[r0 * 8 + j];
            float a1 = s_na[r1 * 8 + j];
#pragma unroll
            for (int nt = 0; nt < 4; ++nt) {
                acc1[nt][0] = fmaf(a0, P[nt][0], acc1[nt][0]);
                acc1[nt][1] = fmaf(a0, P[nt][1], acc1[nt][1]);
                acc1[nt][2] = fmaf(a1, P[nt][2], acc1[nt][2]);
                acc1[nt][3] = fmaf(a1, P[nt][3], acc1[nt][3]);
            }
        }
    }

    // all warps done with TP1 hi region before TP2 lo prefetch (regions alias)
    __syncthreads();
    {   // prefetch TP2 lo chunk 0 (overlaps mid epilogue)
        const char* srcl = (const char*)(&g_U2l[l][0][0][0]);
        for (int idx = tid; idx < 576; idx += 256)
            cp_async16(bB + 9216 + idx * 16, srcl + idx * 16);
        cp_commit();
    }

    // mid: u1 = silu(acc1 + bu1) -> A2 split-bf16 (rows 144B)
#pragma unroll
    for (int nt = 0; nt < 4; ++nt) {
        int c = nh * 32 + nt * 8 + 2 * t;
        float b0 = s_b1[c], b1 = s_b1[c + 1];
        uint32_t hw, lw;
        split_pack(silu_f(acc1[nt][0] + b0), silu_f(acc1[nt][1] + b1), hw, lw);
        uint32_t off = (uint32_t)(r0 * 144 + c * 2);
        *(uint32_t*)(pA2h + off) = hw;
        *(uint32_t*)(pA2l + off) = lw;
        split_pack(silu_f(acc1[nt][2] + b0), silu_f(acc1[nt][3] + b1), hw, lw);
        off = (uint32_t)(r1 * 144 + c * 2);
        *(uint32_t*)(pA2h + off) = hw;
        *(uint32_t*)(pA2l + off) = lw;
    }

    float acc2[4][4];
#pragma unroll
    for (int nt = 0; nt < 4; ++nt)
#pragma unroll
        for (int q = 0; q < 4; ++q) acc2[nt][q] = 0.0f;

    // ---- TP2: K=64 (4 kt), B rows 144B, half-chunk pipelined
    {
        uint32_t shAh = smem_u32_of(pA2h) +
            (uint32_t)((wr * 16 + (lane & 15)) * 144 + ((lane >> 4) & 1) * 16);
        uint32_t shAl = shAh + 9216;
        uint32_t bo0 = (uint32_t)(((lane & 7) + ((lane >> 4) & 1) * 8) * 144 +
                                  ((lane >> 3) & 1) * 16 + nh * 32 * 144);
        uint32_t bBh = bB, bBl = bB + 9216;

        for (int j = 0; j < 8; ++j) {
            cp_wait0();
            __syncthreads();       // also covers A2 writes on first iteration
            {
                const char* srch = (const char*)(&g_U2h[l][j][0][0]);
                for (int idx = tid; idx < 576; idx += 256)
                    cp_async16(bBh + idx * 16, srch + idx * 16);
                cp_commit();
            }

            float P[4][4];
#pragma unroll
            for (int nt = 0; nt < 4; ++nt)
#pragma unroll
                for (int q = 0; q < 4; ++q) P[nt][q] = 0.0f;

#pragma unroll
            for (int kt = 0; kt < 4; ++kt) {
                uint32_t ko = (uint32_t)(kt * 32);
                uint32_t ah[4];
                ldmx4(ah[0], ah[1], ah[2], ah[3], shAh + ko);
#pragma unroll
                for (int p = 0; p < 2; ++p) {
                    uint32_t bo = bo0 + (uint32_t)(p * 16 * 144) + ko;
                    uint32_t bl0, bl1, bl2, bl3;
                    ldmx4(bl0, bl1, bl2, bl3, bBl + bo);
                    mma_bf16(P[2 * p],     ah, bl0, bl1);
                    mma_bf16(P[2 * p + 1], ah, bl2, bl3);
                }
            }

            cp_wait0();
            __syncthreads();
            if (j < 7) {
                const char* srcl = (const char*)(&g_U2l[l][j + 1][0][0]);
                for (int idx = tid; idx < 576; idx += 256)
                    cp_async16(bBl + idx * 16, srcl + idx * 16);
                cp_commit();
            }

#pragma unroll
            for (int kt = 0; kt < 4; ++kt) {
                uint32_t ko = (uint32_t)(kt * 32);
                uint32_t ah[4], al[4];
                ldmx4(ah[0], ah[1], ah[2], ah[3], shAh + ko);
                ldmx4(al[0], al[1], al[2], al[3], shAl + ko);
#pragma unroll
                for (int p = 0; p < 2; ++p) {
                    uint32_t bo = bo0 + (uint32_t)(p * 16 * 144) + ko;
                    uint32_t bh0, bh1, bh2, bh3;
                    ldmx4(bh0, bh1, bh2, bh3, bBh + bo);
                    mma_bf16(P[2 * p],     ah, bh0, bh1);
                    mma_bf16(P[2 * p],     al, bh0, bh1);
                    mma_bf16(P[2 * p + 1], ah, bh2, bh3);
                    mma_bf16(P[2 * p + 1], al, bh2, bh3);
                }
            }

            float a0 = s_na[r0 * 8 + j];
            float a1 = s_na[r1 * 8 + j];
#pragma unroll
            for (int nt = 0; nt < 4; ++nt) {
                acc2[nt][0] = fmaf(a0, P[nt][0], acc2[nt][0]);
                acc2[nt][1] = fmaf(a0, P[nt][1], acc2[nt][1]);
                acc2[nt][2] = fmaf(a1, P[nt][2], acc2[nt][2]);
                acc2[nt][3] = fmaf(a1, P[nt][3], acc2[nt][3]);
            }
        }
    }

    {
        int na = n0 + r0, nb = n0 + r1;
#pragma unroll
        for (int nt = 0; nt < 4; ++nt) {
            int c = nh * 32 + nt * 8 + 2 * t;
            if (na < NN) {
                g_h[na * 64 + c]     += acc2[nt][0] + s_b2[c];
                g_h[na * 64 + c + 1] += acc2[nt][1] + s_b2[c + 1];
            }
            if (nb < NN) {
                g_h[nb * 64 + c]     += acc2[nt][2] + s_b2[c];
                g_h[nb * 64 + c + 1] += acc2[nt][3] + s_b2[c + 1];
            }
        }
    }
}

// ================= pool kernel MMA v2: half-chunk pipelined B ===============
#define PA_A1H 0
#define PA_A1L 9216
#define PA_B   18432
#define PA_A2H 36864
#define PA_A2L 46080
#define PA_NA  55296
#define PA_B1  57344
#define PA_B2  57600
#define PA_BYTES 57856

__global__ void __launch_bounds__(256, 2)
pool_mma_kernel(const float* __restrict__ node_attr, const int* __restrict__ batch,
                const float* __restrict__ bp1, const float* __restrict__ bp2)
{
    extern __shared__ float sm[];
    char* smc = (char*)sm;
    char* pA1h = smc + PA_A1H;
    char* pA1l = smc + PA_A1L;
    char* pA2h = smc + PA_A2H;
    char* pA2l = smc + PA_A2L;
    float* s_na = (float*)(smc + PA_NA);
    float* s_b1 = (float*)(smc + PA_B1);
    float* s_b2 = (float*)(smc + PA_B2);
    uint32_t bBh = smem_u32_of(smc + PA_B);
    uint32_t bBl = bBh + 9216;

    int tid = threadIdx.x;
    int w = tid >> 5, lane = tid & 31;
    int n0 = blockIdx.x * 64;

    // prefetch stage-0 lo chunk 0
    {
        const char* srcl = (const char*)(&g_P1l[0][0][0]);
        for (int idx = tid; idx < 576; idx += 256)
            cp_async16(bBl + idx * 16, srcl + idx * 16);
        cp_commit();
    }

    for (int idx = tid; idx < 512; idx += 256) {
        int row = idx >> 3, j = idx & 7;
        int n = min(n0 + row, NN - 1);
        s_na[idx] = node_attr[n * 8 + j];
    }
    if (tid < 64) {
        s_b1[tid] = bp1[tid];
        s_b2[tid] = bp2[tid];
    }

    for (int idx = tid; idx < 64 * 36; idx += 256) {
        int row = idx / 36, iw = idx - row * 36;
        int n = min(n0 + row, NN - 1);
        int i0 = iw * 2;
        float v0 = (i0 < 64) ? g_h[n * 64 + i0] : 0.0f;
        float v1 = (i0 + 1 < 64) ? g_h[n * 64 + i0 + 1] : 0.0f;
        uint32_t hw, lw;
        split_pack(v0, v1, hw, lw);
        uint32_t off = (uint32_t)(row * 144 + i0 * 2);
        *(uint32_t*)(pA1h + off) = hw;
        *(uint32_t*)(pA1l + off) = lw;
    }
    __syncthreads();

    int wr = w & 3, nh = w >> 2;
    int g = lane >> 2, t = lane & 3;
    int r0 = wr * 16 + g, r1 = r0 + 8;

    uint32_t aoffBase = (uint32_t)((wr * 16 + (lane & 15)) * 144 + ((lane >> 4) & 1) * 16);
    uint32_t bo0 = (uint32_t)(((lane & 7) + ((lane >> 4) & 1) * 8) * 144 +
                              ((lane >> 3) & 1) * 16 + nh * 32 * 144);

    float acc[4][4];

    for (int stage = 0; stage < 2; ++stage) {
        uint32_t shAh = smem_u32_of(stage ? pA2h : pA1h) + aoffBase;
        uint32_t shAl = shAh + 9216;

#pragma unroll
        for (int nt = 0; nt < 4; ++nt)
#pragma unroll
            for (int q = 0; q < 4; ++q) acc[nt][q] = 0.0f;

        for (int j = 0; j < 8; ++j) {
            cp_wait0();
            __syncthreads();
            {
                const char* srch = stage ? (const char*)(&g_P2h[j][0][0])
                                         : (const char*)(&g_P1h[j][0][0]);
                for (int idx = tid; idx < 576; idx += 256)
                    cp_async16(bBh + idx * 16, srch + idx * 16);
                cp_commit();
            }

            float P[4][4];
#pragma unroll
            for (int nt = 0; nt < 4; ++nt)
#pragma unroll
                for (int q = 0; q < 4; ++q) P[nt][q] = 0.0f;

#pragma unroll
            for (int kt = 0; kt < 4; ++kt) {
                uint32_t ko = (uint32_t)(kt * 32);
                uint32_t ah[4];
                ldmx4(ah[0], ah[1], ah[2], ah[3], shAh + ko);
#pragma unroll
                for (int p = 0; p < 2; ++p) {
                    uint32_t bo = bo0 + (uint32_t)(p * 16 * 144) + ko;
                    uint32_t bl0, bl1, bl2, bl3;
                    ldmx4(bl0, bl1, bl2, bl3, bBl + bo);
                    mma_bf16(P[2 * p],     ah, bl0, bl1);
                    mma_bf16(P[2 * p + 1], ah, bl2, bl3);
                }
            }

            cp_wait0();
            __syncthreads();
            if (j < 7) {
                const char* srcl = stage ? (const char*)(&g_P2l[j + 1][0][0])
                                         : (const char*)(&g_P1l[j + 1][0][0]);
                for (int idx = tid; idx < 576; idx += 256)
                    cp_async16(bBl + idx * 16, srcl + idx * 16);
                cp_commit();
            }

#pragma unroll
            for (int kt = 0; kt < 4; ++kt) {
                uint32_t ko = (uint32_t)(kt * 32);
                uint32_t ah[4], al[4];
                ldmx4(ah[0], ah[1], ah[2], ah[3], shAh + ko);
                ldmx4(al[0], al[1], al[2], al[3], shAl + ko);
#pragma unroll
                for (int p = 0; p < 2; ++p) {
                    uint32_t bo = bo0 + (uint32_t)(p * 16 * 144) + ko;
                    uint32_t bh0, bh1, bh2, bh3;
                    ldmx4(bh0, bh1, bh2, bh3, bBh + bo);
                    mma_bf16(P[2 * p],     ah, bh0, bh1);
                    mma_bf16(P[2 * p],     al, bh0, bh1);
                    mma_bf16(P[2 * p + 1], ah, bh2, bh3);
                    mma_bf16(P[2 * p + 1], al, bh2, bh3);
                }
            }

            float a0 = s_na[r0 * 8 + j];
            float a1 = s_na[r1 * 8 + j];
#pragma unroll
            for (int nt = 0; nt < 4; ++nt) {
                acc[nt][0] = fmaf(a0, P[nt][0], acc[nt][0]);
                acc[nt][1] = fmaf(a0, P[nt][1], acc[nt][1]);
                acc[nt][2] = fmaf(a1, P[nt][2], acc[nt][2]);
                acc[nt][3] = fmaf(a1, P[nt][3], acc[nt][3]);
            }
        }

        if (stage == 0) {
            // all warps done with stage-0 hi region before stage-1 lo prefetch
            __syncthreads();
            {
                const char* srcl = (const char*)(&g_P2l[0][0][0]);
                for (int idx = tid; idx < 576; idx += 256)
                    cp_async16(bBl + idx * 16, srcl + idx * 16);
                cp_commit();
            }
#pragma unroll
            for (int nt = 0; nt < 4; ++nt) {
                int c = nh * 32 + nt * 8 + 2 * t;
                float b0 = s_b1[c], b1 = s_b1[c + 1];
                uint32_t hw, lw;
                split_pack(silu_f(acc[nt][0] + b0), silu_f(acc[nt][1] + b1), hw, lw);
                uint32_t off = (uint32_t)(r0 * 144 + c * 2);
                *(uint32_t*)(pA2h + off) = hw;
                *(uint32_t*)(pA2l + off) = lw;
                split_pack(silu_f(acc[nt][2] + b0), silu_f(acc[nt][3] + b1), hw, lw);
                off = (uint32_t)(r1 * 144 + c * 2);
                *(uint32_t*)(pA2h + off) = hw;
                *(uint32_t*)(pA2l + off) = lw;
            }
        }
    }

    {
        int na = n0 + r0, nb = n0 + r1;
        int ba = (na < NN) ? batch[na] : -1;
        int bb2 = (nb < NN) ? batch[nb] : -1;
#pragma unroll
        for (int nt = 0; nt < 4; ++nt) {
            int c = nh * 32 + nt * 8 + 2 * t;
            if (ba >= 0) {
                atomicAdd(&g_pool[ba * 64 + c],     acc[nt][0] + s_b2[c]);
                atomicAdd(&g_pool[ba * 64 + c + 1], acc[nt][1] + s_b2[c + 1]);
            }
            if (bb2 >= 0) {
                atomicAdd(&g_pool[bb2 * 64 + c],     acc[nt][2] + s_b2[c]);
                atomicAdd(&g_pool[bb2 * 64 + c + 1], acc[nt][3] + s_b2[c + 1]);
            }
        }
        if (nh == 0 && t == 0) {
            if (ba >= 0) atomicAdd(&g_cnt[ba], 1.0f);
            if (bb2 >= 0) atomicAdd(&g_cnt[bb2], 1.0f);
        }
    }
}

// ---------------- final tiny post-pool MLP ---------------------------------
__global__ void final_kernel(const float* __restrict__ Wq1, const float* __restrict__ bq1,
                             const float* __restrict__ Wq2, const float* __restrict__ bq2,
                             float* __restrict__ out)
{
    int b = threadIdx.x;
    if (b >= BB) return;
    float c = g_cnt[b];
    if (c < 1.0f) c = 1.0f;
    float g[64];
#pragma unroll
    for (int k = 0; k < 64; ++k) g[k] = g_pool[b * 64 + k] / c;
    float o = bq2[0];
    for (int j = 0; j < 64; ++j) {
        float s = bq1[j];
#pragma unroll
        for (int k = 0; k < 64; ++k) s = fmaf(g[k], Wq1[k * 64 + j], s);
        o = fmaf(silu_f(s), Wq2[j], o);
    }
    out[b] = o;
}

// ---------------- launch ----------------------------------------------------
extern "C" void kernel_launch(void* const* d_in, const int* in_sizes, int n_in,
                              void* d_out, int out_size)
{
    const float* x         = (const float*)d_in[0];
    const int*   edge_index= (const int*)d_in[1];
    const float* edge_attr = (const float*)d_in[2];
    const float* node_attr = (const float*)d_in[3];
    const float* amf       = (const float*)d_in[4];
    const float* anf       = (const float*)d_in[5];
    const int*   batch     = (const int*)d_in[6];
    const float* W_emb     = (const float*)d_in[7];
    const float* b_emb     = (const float*)d_in[8];
    const float* Wm1       = (const float*)d_in[9];
    const float* bm1       = (const float*)d_in[10];
    const float* Wm2       = (const float*)d_in[11];
    const float* bm2       = (const float*)d_in[12];
    const float* Wu1       = (const float*)d_in[13];
    const float* bu1       = (const float*)d_in[14];
    const float* Wu2       = (const float*)d_in[15];
    const float* bu2       = (const float*)d_in[16];
    const float* Wp1       = (const float*)d_in[17];
    const float* bp1       = (const float*)d_in[18];
    const float* Wp2       = (const float*)d_in[19];
    const float* bp2       = (const float*)d_in[20];
    const float* Wq1       = (const float*)d_in[21];
    const float* bq1       = (const float*)d_in[22];
    const float* Wq2       = (const float*)d_in[23];
    const float* bq2       = (const float*)d_in[24];
    float* out = (float*)d_out;

    cudaFuncSetAttribute(msg_kernel_v7,    cudaFuncAttributeMaxDynamicSharedMemorySize, MH_BYTES);
    cudaFuncSetAttribute(nodeT_mma_kernel, cudaFuncAttributeMaxDynamicSharedMemorySize, TM_BYTES);
    cudaFuncSetAttribute(embed_kernel_v4,  cudaFuncAttributeMaxDynamicSharedMemorySize, E4_BYTES);
    cudaFuncSetAttribute(upd_mma_kernel,   cudaFuncAttributeMaxDynamicSharedMemorySize, UA_BYTES);
    cudaFuncSetAttribute(pool_mma_kernel,  cudaFuncAttributeMaxDynamicSharedMemorySize, PA_BYTES);

    void* poolp = nullptr; cudaGetSymbolAddress(&poolp, g_pool);
    void* cntp = nullptr;  cudaGetSymbolAddress(&cntp, g_cnt);

    int tblocks  = (NN + 63) / 64;    // 157
    int eblocks  = EE / 128;          // 1250

    prep_all_kernel<<<2144, 256>>>(Wm1, Wm2, Wu1, Wu2, Wp1, Wp2);
    embed_kernel_v4<<<tblocks, 128, E4_BYTES>>>(x, anf, node_attr, W_emb, b_emb);

    for (int l = 0; l < LL; ++l) {
        nodeT_mma_kernel<<<tblocks, 256, TM_BYTES>>>(l, anf);
        msg_kernel_v7<<<eblocks, 256, MH_BYTES>>>(l, edge_index, edge_attr, amf,
                                                  Wm1, bm1, bm2);
        upd_mma_kernel<<<tblocks, 256, UA_BYTES>>>(l, node_attr, anf, bu1, bu2);
    }

    cudaMemsetAsync(poolp, 0, (size_t)BB * HH * sizeof(float));
    cudaMemsetAsync(cntp, 0, (size_t)BB * sizeof(float));
    pool_mma_kernel<<<tblocks, 256, PA_BYTES>>>(node_attr, batch, bp1, bp2);
    final_kernel<<<1, BB>>>(Wq1, bq1, Wq2, bq2, out);
}

// round 15
// speedup vs baseline: 1.0361x; 1.0361x over previous
#include <cuda_runtime.h>
#include <cuda_bf16.h>
#include <math.h>
#include <stdint.h>

#define NN 10000
#define EE 160000
#define BB 16
#define HH 64
#define AA 8
#define LL 2
#define MSGIN 131
#define UPDIN 129

// ---------------- scratch (device globals) ----------------------------------
__device__ float g_h[NN * HH];
__device__ float g_agg[NN * HH];
__device__ float g_pool[BB * HH];
__device__ float g_cnt[BB];
__device__ float g_T1[NN * 512];
__device__ float g_T2[NN * 512];
// split-bf16 weight planes
__device__ __align__(16) __nv_bfloat16 g_W2h[2][8][64][72];
__device__ __align__(16) __nv_bfloat16 g_W2l[2][8][64][72];
__device__ __align__(16) __nv_bfloat16 g_U1h[2][8][64][152];
__device__ __align__(16) __nv_bfloat16 g_U1l[2][8][64][152];
__device__ __align__(16) __nv_bfloat16 g_U2h[2][8][64][72];
__device__ __align__(16) __nv_bfloat16 g_U2l[2][8][64][72];
__device__ __align__(16) __nv_bfloat16 g_P1h[8][64][72];
__device__ __align__(16) __nv_bfloat16 g_P1l[8][64][72];
__device__ __align__(16) __nv_bfloat16 g_P2h[8][64][72];
__device__ __align__(16) __nv_bfloat16 g_P2l[8][64][72];
// W1 permuted planes for nodeT GEMM
__device__ __align__(16) __nv_bfloat16 g_TWh[2][16][64][88];
__device__ __align__(16) __nv_bfloat16 g_TWl[2][16][64][88];

__device__ __forceinline__ float silu_f(float x) { return x / (1.0f + expf(-x)); }

// ---------------- PTX helpers (generic sm_80+) -------------------------------
__device__ __forceinline__ uint32_t smem_u32_of(const void* p) {
    uint32_t a;
    asm("{ .reg .u64 t; cvta.to.shared.u64 t, %1; cvt.u32.u64 %0, t; }" : "=r"(a) : "l"(p));
    return a;
}
__device__ __forceinline__ void mma_bf16(float (&c)[4], const uint32_t (&a)[4],
                                         uint32_t b0, uint32_t b1) {
    asm volatile(
        "mma.sync.aligned.m16n8k16.row.col.f32.bf16.bf16.f32 "
        "{%0,%1,%2,%3}, {%4,%5,%6,%7}, {%8,%9}, {%0,%1,%2,%3};"
        : "+f"(c[0]), "+f"(c[1]), "+f"(c[2]), "+f"(c[3])
        : "r"(a[0]), "r"(a[1]), "r"(a[2]), "r"(a[3]), "r"(b0), "r"(b1));
}
__device__ __forceinline__ void ldmx4(uint32_t& r0, uint32_t& r1, uint32_t& r2, uint32_t& r3,
                                      uint32_t addr) {
    asm volatile("ldmatrix.sync.aligned.m8n8.x4.shared.b16 {%0,%1,%2,%3}, [%4];"
                 : "=r"(r0), "=r"(r1), "=r"(r2), "=r"(r3) : "r"(addr));
}
__device__ __forceinline__ void cp_async16(uint32_t smem_addr, const void* gptr) {
    asm volatile("cp.async.cg.shared.global [%0], [%1], 16;"
                 :: "r"(smem_addr), "l"(gptr) : "memory");
}
__device__ __forceinline__ void cp_commit() {
    asm volatile("cp.async.commit_group;" ::: "memory");
}
__device__ __forceinline__ void cp_wait0() {
    asm volatile("cp.async.wait_group 0;" ::: "memory");
}
__device__ __forceinline__ uint32_t pack2_bf16(__nv_bfloat16 lo16, __nv_bfloat16 hi16) {
    uint16_t a, b;
    memcpy(&a, &lo16, 2);
    memcpy(&b, &hi16, 2);
    return (uint32_t)a | ((uint32_t)b << 16);
}
__device__ __forceinline__ void split_pack(float v0, float v1, uint32_t& hw, uint32_t& lw) {
    __nv_bfloat16 h0 = __float2bfloat16(v0);
    __nv_bfloat16 h1 = __float2bfloat16(v1);
    __nv_bfloat16 l0 = __float2bfloat16(v0 - __bfloat162float(h0));
    __nv_bfloat16 l1 = __float2bfloat16(v1 - __bfloat162float(h1));
    hw = pack2_bf16(h0, h1);
    lw = pack2_bf16(l0, l1);
}

// ============================================================================
// scalar node-side TP core (embed only)
// ============================================================================
__device__ __forceinline__ void tp4(float (&acc)[4][8], const float* s_in, int stride,
                                    const float* s_W, const float (&av)[4][8],
                                    int nrow0, int kbase, int ilen)
{
    for (int i = 0; i < ilen; ++i) {
        float m0 = s_in[(nrow0 + 0) * stride + i];
        float m1 = s_in[(nrow0 + 1) * stride + i];
        float m2 = s_in[(nrow0 + 2) * stride + i];
        float m3 = s_in[(nrow0 + 3) * stride + i];
        const float* wrow = s_W + i * 512 + kbase;
#pragma unroll
        for (int j = 0; j < 8; ++j) {
            float4 wa = *(const float4*)(wrow + j * 64);
            float4 wb = *(const float4*)(wrow + j * 64 + 4);
            float w[8] = {wa.x, wa.y, wa.z, wa.w, wb.x, wb.y, wb.z, wb.w};
            float c0 = m0 * av[0][j];
            float c1 = m1 * av[1][j];
            float c2 = m2 * av[2][j];
            float c3 = m3 * av[3][j];
#pragma unroll
            for (int t = 0; t < 8; ++t) {
                acc[0][t] = fmaf(c0, w[t], acc[0][t]);
                acc[1][t] = fmaf(c1, w[t], acc[1][t]);
                acc[2][t] = fmaf(c2, w[t], acc[2][t]);
                acc[3][t] = fmaf(c3, w[t], acc[3][t]);
            }
        }
    }
}

__device__ __forceinline__ void stage_w128(float* s_W, const float* Wg, int ibase, int ilen)
{
    const float4* src = (const float4*)(Wg + (size_t)ibase * 512);
    float4* dst = (float4*)s_W;
    int n4 = ilen * 128;
    for (int idx = threadIdx.x; idx < n4; idx += 128) dst[idx] = src[idx];
}

// ================= merged prep kernel =======================================
__global__ void __launch_bounds__(256)
prep_all_kernel(const float* __restrict__ Wm1, const float* __restrict__ Wm2,
                const float* __restrict__ Wu1, const float* __restrict__ Wu2,
                const float* __restrict__ Wp1, const float* __restrict__ Wp2)
{
    int idx = blockIdx.x * 256 + threadIdx.x;
    float v;
    __nv_bfloat16 *ph, *pl;

    if (idx < 65536) {
        int l = idx >> 15, rem = idx & 32767;
        int c = rem >> 12, r2 = rem & 4095;
        int n = r2 >> 6, i = r2 & 63;
        v = Wm2[(size_t)l * 64 * 512 + (size_t)i * 512 + c * 64 + n];
        ph = &g_W2h[l][c][n][i]; pl = &g_W2l[l][c][n][i];
    } else if (idx < 65536 + 155648) {
        int q = idx - 65536;
        int l = q / 77824, rem = q - l * 77824;
        int c = rem / 9728, r2 = rem - c * 9728;
        int n = r2 / 152, i = r2 - n * 152;
        v = (i < UPDIN) ? Wu1[(size_t)l * UPDIN * 512 + (size_t)i * 512 + c * 64 + n] : 0.0f;
        ph = &g_U1h[l][c][n][i]; pl = &g_U1l[l][c][n][i];
    } else if (idx < 65536 + 155648 + 73728) {
        int q = idx - 65536 - 155648;
        int l = q / 36864, rem = q - l * 36864;
        int c = rem / 4608, r2 = rem - c * 4608;
        int n = r2 / 72, i = r2 - n * 72;
        v = (i < 64) ? Wu2[(size_t)l * 64 * 512 + (size_t)i * 512 + c * 64 + n] : 0.0f;
        ph = &g_U2h[l][c][n][i]; pl = &g_U2l[l][c][n][i];
    } else if (idx < 65536 + 155648 + 73728 + 73728) {
        int q = idx - 65536 - 155648 - 73728;
        int sel = q / 36864, rem = q - sel * 36864;
        int c = rem / 4608, r2 = rem - c * 4608;
        int n = r2 / 72, i = r2 - n * 72;
        const float* W = sel ? Wp2 : Wp1;
        v = (i < 64) ? W[(size_t)i * 512 + c * 64 + n] : 0.0f;
        if (sel) { ph = &g_P2h[c][n][i]; pl = &g_P2l[c][n][i]; }
        else     { ph = &g_P1h[c][n][i]; pl = &g_P1l[c][n][i]; }
    } else if (idx < 65536 + 155648 + 73728 + 73728 + 180224) {
        int q = idx - 65536 - 155648 - 73728 - 73728;
        int l = q / 90112, rem = q - l * 90112;
        int c = rem / 5632, r2 = rem - c * 5632;
        int n = r2 / 88, i = r2 - n * 88;
        int g = (c & 7) * 64 + n;
        int j = g & 7, kk = g >> 3;
        int wrow = (c < 8) ? i : (65 + i);
        v = (i < 65) ? Wm1[(size_t)l * MSGIN * 512 + (size_t)wrow * 512 + j * 64 + kk] : 0.0f;
        ph = &g_TWh[l][c][n][i]; pl = &g_TWl[l][c][n][i];
    } else return;

    __nv_bfloat16 h = __float2bfloat16(v);
    *ph = h;
    *pl = __float2bfloat16(v - __bfloat162float(h));
}

// ================= nodeT MMA kernel (round-13, unchanged) ===================
#define TM_AH 0
#define TM_AL 11264
#define TM_B  22528
#define TM_BYTES (22528 + 45056)
#define TRS 176

__global__ void __launch_bounds__(256, 2)
nodeT_mma_kernel(int l, const float* __restrict__ anf)
{
    extern __shared__ float sm[];
    char* smc = (char*)sm;
    char* pAh = smc + TM_AH;
    char* pAl = smc + TM_AL;
    uint32_t bB = smem_u32_of(smc + TM_B);

    int tid = threadIdx.x;
    int w = tid >> 5, lane = tid & 31;
    int n0 = blockIdx.x * 64;

    {
        const char* srch = (const char*)(&g_TWh[l][0][0][0]);
        const char* srcl = (const char*)(&g_TWl[l][0][0][0]);
        for (int idx = tid; idx < 1408; idx += 256) {
            if (idx < 704) cp_async16(bB + idx * 16, srch + idx * 16);
            else cp_async16(bB + 11264 + (idx - 704) * 16, srcl + (idx - 704) * 16);
        }
        cp_commit();
    }

    for (int idx = tid; idx < 64 * 16; idx += 256) {
        int row = idx >> 4, q = idx & 15;
        int n = n0 + row;
        if (n < NN)
            *(float4*)(g_agg + (size_t)n * 64 + q * 4) = make_float4(0.f, 0.f, 0.f, 0.f);
    }

    for (int idx = tid; idx < 64 * 40; idx += 256) {
        int row = idx / 40, iw = idx - row * 40;
        int n = min(n0 + row, NN - 1);
        int i0 = iw * 2;
        float v0 = (i0 < 64) ? g_h[n * 64 + i0] : ((i0 == 64) ? anf[n] : 0.0f);
        float v1 = (i0 + 1 < 64) ? g_h[n * 64 + i0 + 1] : ((i0 + 1 == 64) ? anf[n] : 0.0f);
        uint32_t hw, lw;
        split_pack(v0, v1, hw, lw);
        uint32_t off = (uint32_t)(row * TRS + i0 * 2);
        *(uint32_t*)(pAh + off) = hw;
        *(uint32_t*)(pAl + off) = lw;
    }
    __syncthreads();

    int wr = w & 3, nh = w >> 2;
    int g = lane >> 2, t = lane & 3;
    int r0 = wr * 16 + g, r1 = r0 + 8;

    uint32_t shAh = smem_u32_of(pAh) +
        (uint32_t)((wr * 16 + (lane & 15)) * TRS + ((lane >> 4) & 1) * 16);
    uint32_t shAl = shAh + 11264;
    uint32_t ah[5][4], al[5][4];
#pragma unroll
    for (int kt = 0; kt < 5; ++kt) {
        ldmx4(ah[kt][0], ah[kt][1], ah[kt][2], ah[kt][3], shAh + kt * 32);
        ldmx4(al[kt][0], al[kt][1], al[kt][2], al[kt][3], shAl + kt * 32);
    }

    uint32_t bo0 = (uint32_t)(((lane & 7) + ((lane >> 4) & 1) * 8) * TRS +
                              ((lane >> 3) & 1) * 16 + nh * 32 * TRS);

    for (int c = 0; c < 16; ++c) {
        cp_wait0();
        __syncthreads();
        if (c < 15) {
            const char* srch = (const char*)(&g_TWh[l][c + 1][0][0]);
            const char* srcl = (const char*)(&g_TWl[l][c + 1][0][0]);
            uint32_t nb = bB + ((c + 1) & 1) * 22528;
            for (int idx = tid; idx < 1408; idx += 256) {
                if (idx < 704) cp_async16(nb + idx * 16, srch + idx * 16);
                else cp_async16(nb + 11264 + (idx - 704) * 16, srcl + (idx - 704) * 16);
            }
            cp_commit();
        }

        uint32_t bb = bB + (c & 1) * 22528;

        float acc[4][4];
#pragma unroll
        for (int nt = 0; nt < 4; ++nt)
#pragma unroll
            for (int q = 0; q < 4; ++q) acc[nt][q] = 0.0f;

#pragma unroll
        for (int kt = 0; kt < 5; ++kt) {
            uint32_t ko = (uint32_t)(kt * 32);
#pragma unroll
            for (int p = 0; p < 2; ++p) {
                uint32_t bo = bo0 + (uint32_t)(p * 16 * TRS) + ko;
                uint32_t bh0, bh1, bh2, bh3, bl0, bl1, bl2, bl3;
                ldmx4(bh0, bh1, bh2, bh3, bb + bo);
                ldmx4(bl0, bl1, bl2, bl3, bb + 11264 + bo);
                mma_bf16(acc[2 * p],     ah[kt], bh0, bh1);
                mma_bf16(acc[2 * p],     ah[kt], bl0, bl1);
                mma_bf16(acc[2 * p],     al[kt], bh0, bh1);
                mma_bf16(acc[2 * p + 1], ah[kt], bh2, bh3);
                mma_bf16(acc[2 * p + 1], ah[kt], bl2, bl3);
                mma_bf16(acc[2 * p + 1], al[kt], bh2, bh3);
            }
        }

        float* T = (c < 8) ? g_T1 : g_T2;
        int cb = (c & 7) * 64;
        int na = n0 + r0, nb2 = n0 + r1;
#pragma unroll
        for (int nt = 0; nt < 4; ++nt) {
            int col = cb + nh * 32 + nt * 8 + 2 * t;
            if (na < NN) {
                T[(size_t)na * 512 + col]     = acc[nt][0];
                T[(size_t)na * 512 + col + 1] = acc[nt][1];
            }
            if (nb2 < NN) {
                T[(size_t)nb2 * 512 + col]     = acc[nt][2];
                T[(size_t)nb2 * 512 + col + 1] = acc[nt][3];
            }
        }
    }
}

// ================= msg kernel v7 (unchanged) ================================
#define MH_A_HI 0
#define MH_A_LO 18432
#define MH_B    36864
#define MH_A8   73728
#define MH_WAMF 77824
#define MH_B1   79872
#define MH_B2   80128
#define MH_IDX  80384
#define MH_BYTES 81408

#define ARS 144
#define BRS 144

__global__ void __launch_bounds__(256, 2)
msg_kernel_v7(int l, const int* __restrict__ edge_index, const float* __restrict__ edge_attr,
              const float* __restrict__ amf,
              const float* __restrict__ Wm1, const float* __restrict__ bm1,
              const float* __restrict__ bm2)
{
    extern __shared__ float sm[];
    char*  smc    = (char*)sm;
    char*  pAh    = smc + MH_A_HI;
    char*  pAl    = smc + MH_A_LO;
    float* s_a    = (float*)(smc + MH_A8);
    float* s_wamf = (float*)(smc + MH_WAMF);
    float* s_b1   = (float*)(smc + MH_B1);
    float* s_b2   = (float*)(smc + MH_B2);
    int*   s_src  = (int*)(smc + MH_IDX);
    int*   s_dst  = s_src + 128;

    int tid = threadIdx.x;
    int w = tid >> 5, lane = tid & 31;
    int e_abs0 = blockIdx.x * 128;
    const float* W1l = Wm1 + (size_t)l * MSGIN * 512;

    uint32_t bufBase0 = smem_u32_of(smc + MH_B);
    uint32_t bufBase1 = bufBase0 + 18432;

    {
        const char* srch = (const char*)(&g_W2h[l][0][0][0]);
        const char* srcl = (const char*)(&g_W2l[l][0][0][0]);
        for (int idx = tid; idx < 1152; idx += 256) {
            if (idx < 576) cp_async16(bufBase0 + idx * 16, srch + idx * 16);
            else cp_async16(bufBase0 + 9216 + (idx - 576) * 16, srcl + (idx - 576) * 16);
        }
        cp_commit();
    }

    if (tid < 128) {
        s_src[tid] = edge_index[e_abs0 + tid];
        s_dst[tid] = edge_index[EE + e_abs0 + tid];
    }
    for (int idx = tid; idx < 1024; idx += 256)
        s_a[idx] = edge_attr[(size_t)e_abs0 * 8 + idx];
    for (int idx = tid; idx < 512; idx += 256) {
        int k = idx >> 3, j = idx & 7;
        s_wamf[idx] = W1l[(size_t)130 * 512 + j * 64 + k];
    }
    if (tid < 64) {
        s_b1[tid] = bm1[l * 64 + tid];
        s_b2[tid] = bm2[l * 64 + tid];
    }
    __syncthreads();

    {
        int jb = (lane & 1) * 4;
        int klo = lane >> 1;
#pragma unroll 2
        for (int t = 0; t < 16; ++t) {
            int e = w * 16 + t;
            int d = s_dst[e], sn = s_src[e];
            float amfv = amf[e_abs0 + e];
            float a0 = s_a[e * 8 + jb + 0];
            float a1 = s_a[e * 8 + jb + 1];
            float a2 = s_a[e * 8 + jb + 2];
            float a3 = s_a[e * 8 + jb + 3];
            const float4* T1p = (const float4*)(g_T1 + (size_t)d * 512);
            const float4* T2p = (const float4*)(g_T2 + (size_t)sn * 512);
            const float4* Wap = (const float4*)s_wamf;

            float rk[4];
#pragma unroll
            for (int r = 0; r < 4; ++r) {
                int fi = r * 32 + lane;
                float4 t1 = T1p[fi];
                float4 t2 = T2p[fi];
                float4 wa = Wap[fi];
                float p;
                p  = (t1.x + t2.x + amfv * wa.x) * a0;
                p += (t1.y + t2.y + amfv * wa.y) * a1;
                p += (t1.z + t2.z + amfv * wa.z) * a2;
                p += (t1.w + t2.w + amfv * wa.w) * a3;
                p += __shfl_xor_sync(0xffffffffu, p, 1);
                rk[r] = p;
            }
            if (!(lane & 1)) {
#pragma unroll
                for (int r = 0; r < 4; ++r) {
                    int kk = r * 16 + klo;
                    float v = silu_f(rk[r] + s_b1[kk]);
                    __nv_bfloat16 h = __float2bfloat16(v);
                    __nv_bfloat16 lo = __float2bfloat16(v - __bfloat162float(h));
                    uint32_t off = (uint32_t)(e * ARS + kk * 2);
                    *(__nv_bfloat16*)(pAh + off) = h;
                    *(__nv_bfloat16*)(pAl + off) = lo;
                }
            }
        }
    }
    __syncthreads();

    int g = lane >> 2, t = lane & 3;

    uint32_t aoff = (uint32_t)((w * 16 + (lane & 15)) * ARS + ((lane >> 4) & 1) * 16);
    uint32_t boff = (uint32_t)(((lane & 7) + ((lane >> 4) & 1) * 8) * BRS + ((lane >> 3) & 1) * 16);
    uint32_t shAh = smem_u32_of(pAh) + aoff;
    uint32_t shAl = smem_u32_of(pAl) + aoff;

    uint32_t ah[4][4], al[4][4];
#pragma unroll
    for (int kt = 0; kt < 4; ++kt) {
        ldmx4(ah[kt][0], ah[kt][1], ah[kt][2], ah[kt][3], shAh + kt * 32);
        ldmx4(al[kt][0], al[kt][1], al[kt][2], al[kt][3], shAl + kt * 32);
    }

    int r0 = w * 16 + g, r1 = r0 + 8;

    float acc[8][4];
#pragma unroll
    for (int nt = 0; nt < 8; ++nt)
#pragma unroll
        for (int q = 0; q < 4; ++q) acc[nt][q] = 0.0f;

    for (int j = 0; j < 8; ++j) {
        cp_wait0();
        __syncthreads();
        if (j < 7) {
            const char* srch = (const char*)(&g_W2h[l][j + 1][0][0]);
            const char* srcl = (const char*)(&g_W2l[l][j + 1][0][0]);
            uint32_t nb = ((j + 1) & 1) ? bufBase1 : bufBase0;
            for (int idx = tid; idx < 1152; idx += 256) {
                if (idx < 576) cp_async16(nb + idx * 16, srch + idx * 16);
                else cp_async16(nb + 9216 + (idx - 576) * 16, srcl + (idx - 576) * 16);
            }
            cp_commit();
        }

        uint32_t bb = ((j & 1) ? bufBase1 : bufBase0) + boff;

        float P[8][4];
#pragma unroll
        for (int nt = 0; nt < 8; ++nt)
#pragma unroll
            for (int q = 0; q < 4; ++q) P[nt][q] = 0.0f;

#pragma unroll
        for (int kt = 0; kt < 4; ++kt) {
            uint32_t ko = (uint32_t)(kt * 32);
#pragma unroll
            for (int p = 0; p < 4; ++p) {
                uint32_t bo = (uint32_t)(p * 16 * BRS) + ko;
                uint32_t bh0, bh1, bh2, bh3, bl0, bl1, bl2, bl3;
                ldmx4(bh0, bh1, bh2, bh3, bb + bo);
                ldmx4(bl0, bl1, bl2, bl3, bb + 9216 + bo);
                mma_bf16(P[2 * p],     ah[kt], bh0, bh1);
                mma_bf16(P[2 * p],     ah[kt], bl0, bl1);
                mma_bf16(P[2 * p],     al[kt], bh0, bh1);
                mma_bf16(P[2 * p + 1], ah[kt], bh2, bh3);
                mma_bf16(P[2 * p + 1], ah[kt], bl2, bl3);
                mma_bf16(P[2 * p + 1], al[kt], bh2, bh3);
            }
        }

        float a0 = s_a[r0 * 8 + j];
        float a1 = s_a[r1 * 8 + j];
#pragma unroll
        for (int nt = 0; nt < 8; ++nt) {
            acc[nt][0] = fmaf(a0, P[nt][0], acc[nt][0]);
            acc[nt][1] = fmaf(a0, P[nt][1], acc[nt][1]);
            acc[nt][2] = fmaf(a1, P[nt][2], acc[nt][2]);
            acc[nt][3] = fmaf(a1, P[nt][3], acc[nt][3]);
        }
    }

    {
        int d0 = s_dst[r0], d1 = s_dst[r1];
        float* agg0 = g_agg + (size_t)d0 * 64;
        float* agg1 = g_agg + (size_t)d1 * 64;
#pragma unroll
        for (int nt = 0; nt < 8; ++nt) {
            int c0 = nt * 8 + 2 * t, c1 = c0 + 1;
            atomicAdd(agg0 + c0, silu_f(acc[nt][0] + s_b2[c0]));
            atomicAdd(agg0 + c1, silu_f(acc[nt][1] + s_b2[c1]));
            atomicAdd(agg1 + c0, silu_f(acc[nt][2] + s_b2[c0]));
            atomicAdd(agg1 + c1, silu_f(acc[nt][3] + s_b2[c1]));
        }
    }
}

// ================= embed kernel v4 (unchanged) ==============================
#define E4_OFF_W  0
#define E4_OFF_IN 8704
#define E4_OFF_A  (8704 + 1344)
#define E4_FLOATS (8704 + 1344 + 512)
#define E4_BYTES  (E4_FLOATS * 4)

__global__ void __launch_bounds__(128, 2)
embed_kernel_v4(const float* __restrict__ x, const float* __restrict__ anf,
                const float* __restrict__ node_attr,
                const float* __restrict__ W_emb, const float* __restrict__ b_emb)
{
    extern __shared__ float sm[];
    float* s_W  = sm + E4_OFF_W;
    float* s_in = sm + E4_OFF_IN;
    float* s_a  = sm + E4_OFF_A;

    int tid = threadIdx.x;
    int wid = tid >> 5, lane = tid & 31;
    int n0 = blockIdx.x * 64;

    stage_w128(s_W, W_emb, 0, 17);
    for (int row = wid; row < 64; row += 4) {
        int n = min(n0 + row, NN - 1);
        if (lane < 17)
            s_in[row * 21 + lane] = (lane < 16) ? x[n * 16 + lane] : anf[n];
        if (lane < 8)
            s_a[row * 8 + lane] = node_attr[n * 8 + lane];
    }
    __syncthreads();

    int ng = tid >> 3, kq = tid & 7;
    int nrow0 = ng * 4, kbase = kq * 8;

    float av[4][8];
#pragma unroll
    for (int s = 0; s < 4; ++s)
#pragma unroll
        for (int j = 0; j < 8; ++j) av[s][j] = s_a[(nrow0 + s) * 8 + j];

    float acc[4][8];
#pragma unroll
    for (int t = 0; t < 8; ++t) {
        float b = b_emb[kbase + t];
        acc[0][t] = b; acc[1][t] = b; acc[2][t] = b; acc[3][t] = b;
    }

    tp4(acc, s_in, 21, s_W, av, nrow0, kbase, 17);

#pragma unroll
    for (int s = 0; s < 4; ++s) {
        int n = n0 + nrow0 + s;
        if (n < NN) {
#pragma unroll
            for (int t = 0; t < 8; ++t) g_h[n * 64 + kbase + t] = acc[s][t];
        }
    }
}

// ================= upd kernel MMA (+ fused pool for l==1) ===================
#define UA_A1H 0
#define UA_A1L 19456
#define UA_B   38912
#define UA_A2H 77824
#define UA_A2L 87040
#define UA_NA  96256
#define UA_B1  98304
#define UA_B2  98560
#define UA_BP1 98816
#define UA_BP2 99072
#define UA_BYTES 99328

#define ARS1 304

__device__ __forceinline__ float upd_in_val(int n, int i, const float* anf) {
    if (i < 64) return g_h[n * 64 + i];
    if (i == 64) return anf[n];
    if (i < UPDIN) return g_agg[n * 64 + (i - 65)];
    return 0.0f;
}

template <int DO_POOL>
__global__ void __launch_bounds__(256, 2)
upd_mma_kernel(int l, const float* __restrict__ node_attr, const float* __restrict__ anf,
               const float* __restrict__ bu1, const float* __restrict__ bu2,
               const int* __restrict__ batch,
               const float* __restrict__ bp1, const float* __restrict__ bp2)
{
    extern __shared__ float sm[];
    char* smc = (char*)sm;
    char* pA1h = smc + UA_A1H;
    char* pA1l = smc + UA_A1L;
    char* pA2h = smc + UA_A2H;
    char* pA2l = smc + UA_A2L;
    float* s_na = (float*)(smc + UA_NA);
    float* s_b1 = (float*)(smc + UA_B1);
    float* s_b2 = (float*)(smc + UA_B2);
    float* s_bp1 = (float*)(smc + UA_BP1);
    float* s_bp2 = (float*)(smc + UA_BP2);
    uint32_t bB = smem_u32_of(smc + UA_B);

    int tid = threadIdx.x;
    int w = tid >> 5, lane = tid & 31;
    int n0 = blockIdx.x * 64;

    for (int idx = tid; idx < 512; idx += 256) {
        int row = idx >> 3, j = idx & 7;
        int n = min(n0 + row, NN - 1);
        s_na[idx] = node_attr[n * 8 + j];
    }
    if (tid < 64) {
        s_b1[tid] = bu1[l * 64 + tid];
        s_b2[tid] = bu2[l * 64 + tid];
        if (DO_POOL) {
            s_bp1[tid] = bp1[tid];
            s_bp2[tid] = bp2[tid];
        }
    }

    for (int idx = tid; idx < 64 * 76; idx += 256) {
        int row = idx / 76, iw = idx - row * 76;
        int n = min(n0 + row, NN - 1);
        int i0 = iw * 2;
        float v0 = upd_in_val(n, i0, anf);
        float v1 = upd_in_val(n, i0 + 1, anf);
        uint32_t hw, lw;
        split_pack(v0, v1, hw, lw);
        uint32_t off = (uint32_t)(row * ARS1 + i0 * 2);
        *(uint32_t*)(pA1h + off) = hw;
        *(uint32_t*)(pA1l + off) = lw;
    }
    __syncthreads();

    int wr = w & 3, nh = w >> 2;
    int g = lane >> 2, t = lane & 3;
    int r0 = wr * 16 + g, r1 = r0 + 8;

    uint32_t aoff144 = (uint32_t)((wr * 16 + (lane & 15)) * 144 + ((lane >> 4) & 1) * 16);
    uint32_t bo144 = (uint32_t)(((lane & 7) + ((lane >> 4) & 1) * 8) * 144 +
                                ((lane >> 3) & 1) * 16 + nh * 32 * 144);

    float acc1[4][4];
#pragma unroll
    for (int nt = 0; nt < 4; ++nt)
#pragma unroll
        for (int q = 0; q < 4; ++q) acc1[nt][q] = 0.0f;

    // ---- TP1: K=144 (9 kt), B rows 304B
    {
        uint32_t shAh = smem_u32_of(pA1h) +
            (uint32_t)((wr * 16 + (lane & 15)) * ARS1 + ((lane >> 4) & 1) * 16);
        uint32_t shAl = shAh + 19456;
        uint32_t bo0 = (uint32_t)(((lane & 7) + ((lane >> 4) & 1) * 8) * ARS1 +
                                  ((lane >> 3) & 1) * 16 + nh * 32 * ARS1);
        uint32_t bB_lo = bB + 19456;

        for (int j = 0; j < 8; ++j) {
            __syncthreads();
            const char* srch = (const char*)(&g_U1h[l][j][0][0]);
            const char* srcl = (const char*)(&g_U1l[l][j][0][0]);
            for (int idx = tid; idx < 2432; idx += 256) {
                if (idx < 1216) cp_async16(bB + idx * 16, srch + idx * 16);
                else cp_async16(bB_lo + (idx - 1216) * 16, srcl + (idx - 1216) * 16);
            }
            cp_commit();
            cp_wait0();
            __syncthreads();

            float P[4][4];
#pragma unroll
            for (int nt = 0; nt < 4; ++nt)
#pragma unroll
                for (int q = 0; q < 4; ++q) P[nt][q] = 0.0f;

#pragma unroll
            for (int kt = 0; kt < 9; ++kt) {
                uint32_t ko = (uint32_t)(kt * 32);
                uint32_t ah[4], al[4];
                ldmx4(ah[0], ah[1], ah[2], ah[3], shAh + ko);
                ldmx4(al[0], al[1], al[2], al[3], shAl + ko);
#pragma unroll
                for (int p = 0; p < 2; ++p) {
                    uint32_t bo = bo0 + (uint32_t)(p * 16 * ARS1) + ko;
                    uint32_t bh0, bh1, bh2, bh3, bl0, bl1, bl2, bl3;
                    ldmx4(bh0, bh1, bh2, bh3, bB + bo);
                    ldmx4(bl0, bl1, bl2, bl3, bB_lo + bo);
                    mma_bf16(P[2 * p],     ah, bh0, bh1);
                    mma_bf16(P[2 * p],     ah, bl0, bl1);
                    mma_bf16(P[2 * p],     al, bh0, bh1);
                    mma_bf16(P[2 * p + 1], ah, bh2, bh3);
                    mma_bf16(P[2 * p + 1], ah, bl2, bl3);
                    mma_bf16(P[2 * p + 1], al, bh2, bh3);
                }
            }

            float a0 = s_na[r0 * 8 + j];
            float a1 = s_na[r1 * 8 + j];
#pragma unroll
            for (int nt = 0; nt < 4; ++nt) {
                acc1[nt][0] = fmaf(a0, P[nt][0], acc1[nt][0]);
                acc1[nt][1] = fmaf(a0, P[nt][1], acc1[nt][1]);
                acc1[nt][2] = fmaf(a1, P[nt][2], acc1[nt][2]);
                acc1[nt][3] = fmaf(a1, P[nt][3], acc1[nt][3]);
            }
        }
    }

    // mid: u1 = silu(acc1 + bu1) -> A2 split (rows 144B)
    __syncthreads();
#pragma unroll
    for (int nt = 0; nt < 4; ++nt) {
        int c = nh * 32 + nt * 8 + 2 * t;
        float b0 = s_b1[c], b1 = s_b1[c + 1];
        uint32_t hw, lw;
        split_pack(silu_f(acc1[nt][0] + b0), silu_f(acc1[nt][1] + b1), hw, lw);
        uint32_t off = (uint32_t)(r0 * 144 + c * 2);
        *(uint32_t*)(pA2h + off) = hw;
        *(uint32_t*)(pA2l + off) = lw;
        split_pack(silu_f(acc1[nt][2] + b0), silu_f(acc1[nt][3] + b1), hw, lw);
        off = (uint32_t)(r1 * 144 + c * 2);
        *(uint32_t*)(pA2h + off) = hw;
        *(uint32_t*)(pA2l + off) = lw;
    }

    float acc2[4][4];
#pragma unroll
    for (int nt = 0; nt < 4; ++nt)
#pragma unroll
        for (int q = 0; q < 4; ++q) acc2[nt][q] = 0.0f;

    // ---- TP2: K=64 (4 kt), B rows 144B
    {
        uint32_t shAh = smem_u32_of(pA2h) + aoff144;
        uint32_t shAl = shAh + 9216;
        uint32_t bB_lo = bB + 9216;

        for (int j = 0; j < 8; ++j) {
            __syncthreads();
            const char* srch = (const char*)(&g_U2h[l][j][0][0]);
            const char* srcl = (const char*)(&g_U2l[l][j][0][0]);
            for (int idx = tid; idx < 1152; idx += 256) {
                if (idx < 576) cp_async16(bB + idx * 16, srch + idx * 16);
                else cp_async16(bB_lo + (idx - 576) * 16, srcl + (idx - 576) * 16);
            }
            cp_commit();
            cp_wait0();
            __syncthreads();

            float P[4][4];
#pragma unroll
            for (int nt = 0; nt < 4; ++nt)
#pragma unroll
                for (int q = 0; q < 4; ++q) P[nt][q] = 0.0f;

#pragma unroll
            for (int kt = 0; kt < 4; ++kt) {
                uint32_t ko = (uint32_t)(kt * 32);
                uint32_t ah[4], al[4];
                ldmx4(ah[0], ah[1], ah[2], ah[3], shAh + ko);
                ldmx4(al[0], al[1], al[2], al[3], shAl + ko);
#pragma unroll
                for (int p = 0; p < 2; ++p) {
                    uint32_t bo = bo144 + (uint32_t)(p * 16 * 144) + ko;
                    uint32_t bh0, bh1, bh2, bh3, bl0, bl1, bl2, bl3;
                    ldmx4(bh0, bh1, bh2, bh3, bB + bo);
                    ldmx4(bl0, bl1, bl2, bl3, bB_lo + bo);
                    mma_bf16(P[2 * p],     ah, bh0, bh1);
                    mma_bf16(P[2 * p],     ah, bl0, bl1);
                    mma_bf16(P[2 * p],     al, bh0, bh1);
                    mma_bf16(P[2 * p + 1], ah, bh2, bh3);
                    mma_bf16(P[2 * p + 1], ah, bl2, bl3);
                    mma_bf16(P[2 * p + 1], al, bh2, bh3);
                }
            }

            float a0 = s_na[r0 * 8 + j];
            float a1 = s_na[r1 * 8 + j];
#pragma unroll
            for (int nt = 0; nt < 4; ++nt) {
                acc2[nt][0] = fmaf(a0, P[nt][0], acc2[nt][0]);
                acc2[nt][1] = fmaf(a0, P[nt][1], acc2[nt][1]);
                acc2[nt][2] = fmaf(a1, P[nt][2], acc2[nt][2]);
                acc2[nt][3] = fmaf(a1, P[nt][3], acc2[nt][3]);
            }
        }
    }

    if (!DO_POOL) {
        // epilogue: h += u2 (exclusive per (n,c))
        int na = n0 + r0, nb = n0 + r1;
#pragma unroll
        for (int nt = 0; nt < 4; ++nt) {
            int c = nh * 32 + nt * 8 + 2 * t;
            if (na < NN) {
                g_h[na * 64 + c]     += acc2[nt][0] + s_b2[c];
                g_h[na * 64 + c + 1] += acc2[nt][1] + s_b2[c + 1];
            }
            if (nb < NN) {
                g_h[nb * 64 + c]     += acc2[nt][2] + s_b2[c];
                g_h[nb * 64 + c + 1] += acc2[nt][3] + s_b2[c + 1];
            }
        }
        return;
    }

    // ===================== fused pool path (l == 1) =========================
    // h_new stays on-chip: write split-bf16 into pool A region (pA1, 144B rows)
    __syncthreads();   // everyone done reading pA2/bB in TP2
    {
        int na = min(n0 + r0, NN - 1), nb = min(n0 + r1, NN - 1);
#pragma unroll
        for (int nt = 0; nt < 4; ++nt) {
            int c = nh * 32 + nt * 8 + 2 * t;
            float h0 = g_h[na * 64 + c]     + acc2[nt][0] + s_b2[c];
            float h1 = g_h[na * 64 + c + 1] + acc2[nt][1] + s_b2[c + 1];
            uint32_t hw, lw;
            split_pack(h0, h1, hw, lw);
            uint32_t off = (uint32_t)(r0 * 144 + c * 2);
            *(uint32_t*)(pA1h + off) = hw;
            *(uint32_t*)(pA1h + 9216 + off) = lw;
            h0 = g_h[nb * 64 + c]     + acc2[nt][2] + s_b2[c];
            h1 = g_h[nb * 64 + c + 1] + acc2[nt][3] + s_b2[c + 1];
            split_pack(h0, h1, hw, lw);
            off = (uint32_t)(r1 * 144 + c * 2);
            *(uint32_t*)(pA1h + off) = hw;
            *(uint32_t*)(pA1h + 9216 + off) = lw;
        }
    }
    __syncthreads();

    float accp[4][4];
    uint32_t bB_lo = bB + 9216;

    for (int stage = 0; stage < 2; ++stage) {
        uint32_t shAh = smem_u32_of(stage ? pA2h : pA1h) + aoff144;
        uint32_t shAl = shAh + 9216;

#pragma unroll
        for (int nt = 0; nt < 4; ++nt)
#pragma unroll
            for (int q = 0; q < 4; ++q) accp[nt][q] = 0.0f;

        for (int j = 0; j < 8; ++j) {
            __syncthreads();
            const char* srch = stage ? (const char*)(&g_P2h[j][0][0])
                                     : (const char*)(&g_P1h[j][0][0]);
            const char* srcl = stage ? (const char*)(&g_P2l[j][0][0])
                                     : (const char*)(&g_P1l[j][0][0]);
            for (int idx = tid; idx < 1152; idx += 256) {
                if (idx < 576) cp_async16(bB + idx * 16, srch + idx * 16);
                else cp_async16(bB_lo + (idx - 576) * 16, srcl + (idx - 576) * 16);
            }
            cp_commit();
            cp_wait0();
            __syncthreads();

            float P[4][4];
#pragma unroll
            for (int nt = 0; nt < 4; ++nt)
#pragma unroll
                for (int q = 0; q < 4; ++q) P[nt][q] = 0.0f;

#pragma unroll
            for (int kt = 0; kt < 4; ++kt) {
                uint32_t ko = (uint32_t)(kt * 32);
                uint32_t ah[4], al[4];
                ldmx4(ah[0], ah[1], ah[2], ah[3], shAh + ko);
                ldmx4(al[0], al[1], al[2], al[3], shAl + ko);
#pragma unroll
                for (int p = 0; p < 2; ++p) {
                    uint32_t bo = bo144 + (uint32_t)(p * 16 * 144) + ko;
                    uint32_t bh0, bh1, bh2, bh3, bl0, bl1, bl2, bl3;
                    ldmx4(bh0, bh1, bh2, bh3, bB + bo);
                    ldmx4(bl0, bl1, bl2, bl3, bB_lo + bo);
                    mma_bf16(P[2 * p],     ah, bh0, bh1);
                    mma_bf16(P[2 * p],     ah, bl0, bl1);
                    mma_bf16(P[2 * p],     al, bh0, bh1);
                    mma_bf16(P[2 * p + 1], ah, bh2, bh3);
                    mma_bf16(P[2 * p + 1], ah, bl2, bl3);
                    mma_bf16(P[2 * p + 1], al, bh2, bh3);
                }
            }

            float a0 = s_na[r0 * 8 + j];
            float a1 = s_na[r1 * 8 + j];
#pragma unroll
            for (int nt = 0; nt < 4; ++nt) {
                accp[nt][0] = fmaf(a0, P[nt][0], accp[nt][0]);
                accp[nt][1] = fmaf(a0, P[nt][1], accp[nt][1]);
                accp[nt][2] = fmaf(a1, P[nt][2], accp[nt][2]);
                accp[nt][3] = fmaf(a1, P[nt][3], accp[nt][3]);
            }
        }

        if (stage == 0) {
            __syncthreads();   // all warps done with bB reads and pA2 not yet overwritten
#pragma unroll
            for (int nt = 0; nt < 4; ++nt) {
                int c = nh * 32 + nt * 8 + 2 * t;
                float b0 = s_bp1[c], b1 = s_bp1[c + 1];
                uint32_t hw, lw;
                split_pack(silu_f(accp[nt][0] + b0), silu_f(accp[nt][1] + b1), hw, lw);
                uint32_t off = (uint32_t)(r0 * 144 + c * 2);
                *(uint32_t*)(pA2h + off) = hw;
                *(uint32_t*)(pA2l + off) = lw;
                split_pack(silu_f(accp[nt][2] + b0), silu_f(accp[nt][3] + b1), hw, lw);
                off = (uint32_t)(r1 * 144 + c * 2);
                *(uint32_t*)(pA2h + off) = hw;
                *(uint32_t*)(pA2l + off) = lw;
            }
        }
    }

    // pool epilogue: atomic scatter + counts
    {
        int na = n0 + r0, nb = n0 + r1;
        int ba = (na < NN) ? batch[na] : -1;
        int bb2 = (nb < NN) ? batch[nb] : -1;
#pragma unroll
        for (int nt = 0; nt < 4; ++nt) {
            int c = nh * 32 + nt * 8 + 2 * t;
            if (ba >= 0) {
                atomicAdd(&g_pool[ba * 64 + c],     accp[nt][0] + s_bp2[c]);
                atomicAdd(&g_pool[ba * 64 + c + 1], accp[nt][1] + s_bp2[c + 1]);
            }
            if (bb2 >= 0) {
                atomicAdd(&g_pool[bb2 * 64 + c],     accp[nt][2] + s_bp2[c]);
                atomicAdd(&g_pool[bb2 * 64 + c + 1], accp[nt][3] + s_bp2[c + 1]);
            }
        }
        if (nh == 0 && t == 0) {
            if (ba >= 0) atomicAdd(&g_cnt[ba], 1.0f);
            if (bb2 >= 0) atomicAdd(&g_cnt[bb2], 1.0f);
        }
    }
}

// ---------------- final tiny post-pool MLP ---------------------------------
__global__ void final_kernel(const float* __restrict__ Wq1, const float* __restrict__ bq1,
                             const float* __restrict__ Wq2, const float* __restrict__ bq2,
                             float* __restrict__ out)
{
    int b = threadIdx.x;
    if (b >= BB) return;
    float c = g_cnt[b];
    if (c < 1.0f) c = 1.0f;
    float g[64];
#pragma unroll
    for (int k = 0; k < 64; ++k) g[k] = g_pool[b * 64 + k] / c;
    float o = bq2[0];
    for (int j = 0; j < 64; ++j) {
        float s = bq1[j];
#pragma unroll
        for (int k = 0; k < 64; ++k) s = fmaf(g[k], Wq1[k * 64 + j], s);
        o = fmaf(silu_f(s), Wq2[j], o);
    }
    out[b] = o;
}

// ---------------- launch ----------------------------------------------------
extern "C" void kernel_launch(void* const* d_in, const int* in_sizes, int n_in,
                              void* d_out, int out_size)
{
    const float* x         = (const float*)d_in[0];
    const int*   edge_index= (const int*)d_in[1];
    const float* edge_attr = (const float*)d_in[2];
    const float* node_attr = (const float*)d_in[3];
    const float* amf       = (const float*)d_in[4];
    const float* anf       = (const float*)d_in[5];
    const int*   batch     = (const int*)d_in[6];
    const float* W_emb     = (const float*)d_in[7];
    const float* b_emb     = (const float*)d_in[8];
    const float* Wm1       = (const float*)d_in[9];
    const float* bm1       = (const float*)d_in[10];
    const float* Wm2       = (const float*)d_in[11];
    const float* bm2       = (const float*)d_in[12];
    const float* Wu1       = (const float*)d_in[13];
    const float* bu1       = (const float*)d_in[14];
    const float* Wu2       = (const float*)d_in[15];
    const float* bu2       = (const float*)d_in[16];
    const float* Wp1       = (const float*)d_in[17];
    const float* bp1       = (const float*)d_in[18];
    const float* Wp2       = (const float*)d_in[19];
    const float* bp2       = (const float*)d_in[20];
    const float* Wq1       = (const float*)d_in[21];
    const float* bq1       = (const float*)d_in[22];
    const float* Wq2       = (const float*)d_in[23];
    const float* bq2       = (const float*)d_in[24];
    float* out = (float*)d_out;

    cudaFuncSetAttribute(msg_kernel_v7,      cudaFuncAttributeMaxDynamicSharedMemorySize, MH_BYTES);
    cudaFuncSetAttribute(nodeT_mma_kernel,   cudaFuncAttributeMaxDynamicSharedMemorySize, TM_BYTES);
    cudaFuncSetAttribute(embed_kernel_v4,    cudaFuncAttributeMaxDynamicSharedMemorySize, E4_BYTES);
    cudaFuncSetAttribute(upd_mma_kernel<0>,  cudaFuncAttributeMaxDynamicSharedMemorySize, UA_BYTES);
    cudaFuncSetAttribute(upd_mma_kernel<1>,  cudaFuncAttributeMaxDynamicSharedMemorySize, UA_BYTES);

    void* poolp = nullptr; cudaGetSymbolAddress(&poolp, g_pool);
    void* cntp = nullptr;  cudaGetSymbolAddress(&cntp, g_cnt);

    int tblocks  = (NN + 63) / 64;    // 157
    int eblocks  = EE / 128;          // 1250

    cudaMemsetAsync(poolp, 0, (size_t)BB * HH * sizeof(float));
    cudaMemsetAsync(cntp, 0, (size_t)BB * sizeof(float));
    prep_all_kernel<<<2144, 256>>>(Wm1, Wm2, Wu1, Wu2, Wp1, Wp2);
    embed_kernel_v4<<<tblocks, 128, E4_BYTES>>>(x, anf, node_attr, W_emb, b_emb);

    // layer 0
    nodeT_mma_kernel<<<tblocks, 256, TM_BYTES>>>(0, anf);
    msg_kernel_v7<<<eblocks, 256, MH_BYTES>>>(0, edge_index, edge_attr, amf, Wm1, bm1, bm2);
    upd_mma_kernel<0><<<tblocks, 256, UA_BYTES>>>(0, node_attr, anf, bu1, bu2,
                                                  batch, bp1, bp2);
    // layer 1 (+ fused pool)
    nodeT_mma_kernel<<<tblocks, 256, TM_BYTES>>>(1, anf);
    msg_kernel_v7<<<eblocks, 256, MH_BYTES>>>(1, edge_index, edge_attr, amf, Wm1, bm1, bm2);
    upd_mma_kernel<1><<<tblocks, 256, UA_BYTES>>>(1, node_attr, anf, bu1, bu2,
                                                  batch, bp1, bp2);

    final_kernel<<<1, BB>>>(Wq1, bq1, Wq2, bq2, out);
}